// round 7
// baseline (speedup 1.0000x reference)
#include <cuda_runtime.h>
#include <cuda_bf16.h>

// IDW interpolation, POWER=2:  w = 1/d^2 (sqrt cancels).
//
// Round 5: FUSED station-split. Round 4's separate finalize kernel cost
// 5.9us + 9.4MB of DRAM round-trip for zero compute. Now one kernel:
// each block owns 32 point-packs (64 points); its 8 warps each process a
// 64-station split (32 station pairs) for all 32 packs; partial
// (sum_w, sum_wv) go to 4KB of smem; warp 0 reduces 8 partials, divides,
// stores. Deterministic (fixed reduction order), no global scratch.
// 32768 warps total (~48 resident/SM over ~4.6 waves).
//
// Math per pair of stations (d2 values a,b), f32x2-packed over 2 points:
//   w1+w2       = (a+b)/(a*b)          -> 1 MUFU.RCP per 2 stations
//   w1*v1+w2*v2 = (v1*b + v2*a)/(a*b)
// d==0: fold +1e-12 into d^2 (dominating weight, same ratio, no branch,
// pair product can't underflow).

#define NSTATIONS 512
#define SPLITS 8
#define PAIRS_PER_SPLIT 32             // 64 stations per split
#define PACKS_PER_BLOCK 32             // 64 grid points per block
#define TPB 256                        // SPLITS * PACKS_PER_BLOCK
#define NPACKS 131072                  // total points / 2

typedef unsigned long long u64;

__device__ __forceinline__ u64 f2_pack(float lo, float hi) {
    u64 r; asm("mov.b64 %0, {%1, %2};" : "=l"(r) : "f"(lo), "f"(hi)); return r;
}
__device__ __forceinline__ void f2_unpack(u64 a, float& lo, float& hi) {
    asm("mov.b64 {%0, %1}, %2;" : "=f"(lo), "=f"(hi) : "l"(a));
}
__device__ __forceinline__ u64 f2_add(u64 a, u64 b) {
    u64 r; asm("add.rn.f32x2 %0, %1, %2;" : "=l"(r) : "l"(a), "l"(b)); return r;
}
__device__ __forceinline__ u64 f2_mul(u64 a, u64 b) {
    u64 r; asm("mul.rn.f32x2 %0, %1, %2;" : "=l"(r) : "l"(a), "l"(b)); return r;
}
__device__ __forceinline__ u64 f2_fma(u64 a, u64 b, u64 c) {
    u64 r; asm("fma.rn.f32x2 %0, %1, %2, %3;" : "=l"(r) : "l"(a), "l"(b), "l"(c)); return r;
}
__device__ __forceinline__ float frcp(float a) {
    float r; asm("rcp.approx.f32 %0, %1;" : "=f"(r) : "f"(a)); return r;
}
__device__ __forceinline__ u64 f2_rcp(u64 a) {
    float lo, hi; f2_unpack(a, lo, hi);
    return f2_pack(frcp(lo), frcp(hi));
}

__global__ __launch_bounds__(TPB) void idw_fused(
    const float* __restrict__ station_coords,  // (B, S, 2)
    const float* __restrict__ station_values,  // (B, S)
    const float* __restrict__ grid_points,     // (B, P, 2)
    float* __restrict__ out,                   // (B, P) flat
    int P)
{
    // All 512 stations as 256 pairs, 6 u64 each (3 x 16B -> LDS.128):
    //   [0]=(-x1,-x1) [1]=(-y1,-y1) [2]=(-x2,-x2) [3]=(-y2,-y2) [4]=(v1,v1) [5]=(v2,v2)
    __shared__ u64 sh[(NSTATIONS / 2) * 6];        // 12 KB
    __shared__ float4 red[TPB];                    // 4 KB partials

    const int tid   = threadIdx.x;
    const int split = tid >> 5;                    // 0..7 (== warp id)
    const int lane  = tid & 31;                    // pack slot within block
    const int pack  = blockIdx.x * PACKS_PER_BLOCK + lane;
    const int base  = pack * 2;                    // global point id
    const int b     = base / P;  // 64 points/block divides P: one batch per block

    // Stage all 512 stations (2 per thread)
    #pragma unroll
    for (int s = tid; s < NSTATIONS; s += TPB) {
        const float2 c = reinterpret_cast<const float2*>(
            station_coords + (size_t)b * NSTATIONS * 2)[s];
        const float v = station_values[(size_t)b * NSTATIONS + s];
        const int p = s >> 1, w = s & 1;
        sh[p * 6 + w * 2 + 0] = f2_pack(-c.x, -c.x);
        sh[p * 6 + w * 2 + 1] = f2_pack(-c.y, -c.y);
        sh[p * 6 + 4 + w]     = f2_pack(v, v);
    }
    __syncthreads();

    // 2 grid points = 1 float4 (coalesced within each warp)
    const float4 a0 = reinterpret_cast<const float4*>(grid_points)[pack];
    const u64 gx = f2_pack(a0.x, a0.z);
    const u64 gy = f2_pack(a0.y, a0.w);

    const u64 eps2 = f2_pack(1e-12f, 1e-12f);
    u64 ws = 0ull, vs = 0ull;  // packed (0,0)

    const ulonglong2* sh2 = reinterpret_cast<const ulonglong2*>(sh)
                          + (size_t)split * PAIRS_PER_SPLIT * 3;

    #pragma unroll 8
    for (int p = 0; p < PAIRS_PER_SPLIT; p++) {
        ulonglong2 c1 = sh2[p * 3 + 0];  // (nx1, ny1)  LDS.128 broadcast
        ulonglong2 c2 = sh2[p * 3 + 1];  // (nx2, ny2)
        ulonglong2 vv = sh2[p * 3 + 2];  // (vv1, vv2)

        u64 dx1 = f2_add(gx, c1.x);
        u64 dy1 = f2_add(gy, c1.y);
        u64 da  = f2_fma(dy1, dy1, eps2);
        da      = f2_fma(dx1, dx1, da);        // a = d2 of station 1
        u64 dx2 = f2_add(gx, c2.x);
        u64 dy2 = f2_add(gy, c2.y);
        u64 db  = f2_fma(dy2, dy2, eps2);
        db      = f2_fma(dx2, dx2, db);        // b = d2 of station 2
        u64 sum  = f2_add(da, db);             // a + b
        u64 prod = f2_mul(da, db);             // a * b
        u64 num  = f2_mul(vv.x, db);
        num      = f2_fma(vv.y, da, num);      // v1*b + v2*a
        u64 r    = f2_rcp(prod);               // 2x MUFU.RCP per 2 stations
        ws = f2_fma(sum, r, ws);
        vs = f2_fma(num, r, vs);
    }

    // Partials -> smem, layout red[split*32 + lane]
    float w0, w1, n0, n1;
    f2_unpack(ws, w0, w1);
    f2_unpack(vs, n0, n1);
    red[split * PACKS_PER_BLOCK + lane] = make_float4(w0, w1, n0, n1);
    __syncthreads();

    // Warp 0 reduces 8 splits (fixed order -> deterministic) and stores
    if (tid < PACKS_PER_BLOCK) {
        float4 acc = red[tid];
        #pragma unroll
        for (int k = 1; k < SPLITS; k++) {
            float4 t = red[k * PACKS_PER_BLOCK + tid];  // conflict-free LDS.128
            acc.x += t.x; acc.y += t.y; acc.z += t.z; acc.w += t.w;
        }
        float2 r;
        r.x = acc.z * frcp(acc.x);
        r.y = acc.w * frcp(acc.y);
        reinterpret_cast<float2*>(out)[blockIdx.x * PACKS_PER_BLOCK + tid] = r;
    }
}

extern "C" void kernel_launch(void* const* d_in, const int* in_sizes, int n_in,
                              void* d_out, int out_size) {
    const float* station_coords = (const float*)d_in[0];  // (B,S,2)
    const float* station_values = (const float*)d_in[1];  // (B,S)
    const float* grid_points    = (const float*)d_in[2];  // (B,P,2)
    float* out = (float*)d_out;

    const int S = NSTATIONS;                 // 512 per problem spec
    const int B = in_sizes[1] / S;           // 2
    const int P = in_sizes[2] / (B * 2);     // 131072

    const int blocks = NPACKS / PACKS_PER_BLOCK;  // 4096 blocks, 32768 warps
    idw_fused<<<blocks, TPB>>>(station_coords, station_values, grid_points,
                               out, P);
}

// round 8
// speedup vs baseline: 1.0435x; 1.0435x over previous
#include <cuda_runtime.h>
#include <cuda_bf16.h>

// IDW interpolation, POWER=2:  w = 1/d^2 (sqrt cancels).
//
// Round 8: fused station-split (R7) + 2 packs (4 points) per thread.
// R7 evidence: fma pipe 59.3% / alu 36.4% matches 9 FMUL2/FFMA2 + 5 FADD2
// per body at rt=2; issue stuck at 68.7% from serial LDS->FP->RCP->FMA
// chains (~50 cyc deep vs 22 slots). Two independent point-pack chains per
// loop body double the ILP and amortize the 3 LDS.128 over 2x math
// (40 slots per 2-stations-x-4-points vs 44). Staging: one station pair
// per thread, LDG.128 + 3 pre-packed STS.128.
//
// Pairing identity for d2 values a,b (1 rcp per 2 stations per point):
//   w1+w2       = (a+b)/(a*b)
//   w1*v1+w2*v2 = (v1*b + v2*a)/(a*b)
// d==0: fold +1e-12 into d^2 (dominating weight -> same ratio; no branch;
// pair product can't underflow).

#define NSTATIONS 512
#define SPLITS 8
#define PAIRS_PER_SPLIT 32             // 64 stations per split-warp
#define PACKS_PER_BLOCK 64             // 128 grid points per block
#define TPB 256                        // 8 warps: split = warp id
#define NPACKS 131072                  // total points / 2

typedef unsigned long long u64;

__device__ __forceinline__ u64 f2_pack(float lo, float hi) {
    u64 r; asm("mov.b64 %0, {%1, %2};" : "=l"(r) : "f"(lo), "f"(hi)); return r;
}
__device__ __forceinline__ void f2_unpack(u64 a, float& lo, float& hi) {
    asm("mov.b64 {%0, %1}, %2;" : "=f"(lo), "=f"(hi) : "l"(a));
}
__device__ __forceinline__ u64 f2_add(u64 a, u64 b) {
    u64 r; asm("add.rn.f32x2 %0, %1, %2;" : "=l"(r) : "l"(a), "l"(b)); return r;
}
__device__ __forceinline__ u64 f2_mul(u64 a, u64 b) {
    u64 r; asm("mul.rn.f32x2 %0, %1, %2;" : "=l"(r) : "l"(a), "l"(b)); return r;
}
__device__ __forceinline__ u64 f2_fma(u64 a, u64 b, u64 c) {
    u64 r; asm("fma.rn.f32x2 %0, %1, %2, %3;" : "=l"(r) : "l"(a), "l"(b), "l"(c)); return r;
}
__device__ __forceinline__ float frcp(float a) {
    float r; asm("rcp.approx.f32 %0, %1;" : "=f"(r) : "f"(a)); return r;
}
__device__ __forceinline__ u64 f2_rcp(u64 a) {
    float lo, hi; f2_unpack(a, lo, hi);
    return f2_pack(frcp(lo), frcp(hi));
}

__global__ __launch_bounds__(TPB) void idw_fused(
    const float* __restrict__ station_coords,  // (B, S, 2)
    const float* __restrict__ station_values,  // (B, S)
    const float* __restrict__ grid_points,     // (B, P, 2)
    float* __restrict__ out,                   // (B, P) flat
    int P)
{
    // 256 station pairs, 6 u64 each (3 x 16B -> LDS.128):
    //  [0]=(-x1,-x1) [1]=(-y1,-y1) [2]=(-x2,-x2) [3]=(-y2,-y2) [4]=(v1,v1) [5]=(v2,v2)
    __shared__ u64 sh[(NSTATIONS / 2) * 6];        // 12 KB
    __shared__ float4 red[SPLITS * PACKS_PER_BLOCK];  // 8 KB partials

    const int tid   = threadIdx.x;
    const int split = tid >> 5;                    // warp id, 0..7
    const int lane  = tid & 31;
    const int packbase = blockIdx.x * PACKS_PER_BLOCK;
    // Each thread owns packs (lane) and (lane+32) of this block.
    const int b = (packbase * 2) / P;  // 128 points/block divides P: one batch

    // Stage: one station pair per thread. Coords of pair t = 4 consecutive
    // floats (16B-aligned) -> LDG.128; values -> LDG.64; 3x STS.128.
    {
        const float4 c = reinterpret_cast<const float4*>(
            station_coords + (size_t)b * NSTATIONS * 2)[tid];
        const float2 v = reinterpret_cast<const float2*>(
            station_values + (size_t)b * NSTATIONS)[tid];
        ulonglong2* dst = reinterpret_cast<ulonglong2*>(sh + tid * 6);
        dst[0] = make_ulonglong2(f2_pack(-c.x, -c.x), f2_pack(-c.y, -c.y));
        dst[1] = make_ulonglong2(f2_pack(-c.z, -c.z), f2_pack(-c.w, -c.w));
        dst[2] = make_ulonglong2(f2_pack(v.x, v.x),   f2_pack(v.y, v.y));
    }
    __syncthreads();

    // Two packs per thread: coalesced float4 loads (stride 32 across warp)
    const float4 a0 = reinterpret_cast<const float4*>(grid_points)[packbase + lane];
    const float4 a1 = reinterpret_cast<const float4*>(grid_points)[packbase + 32 + lane];
    const u64 gx0 = f2_pack(a0.x, a0.z), gy0 = f2_pack(a0.y, a0.w);
    const u64 gx1 = f2_pack(a1.x, a1.z), gy1 = f2_pack(a1.y, a1.w);

    const u64 eps2 = f2_pack(1e-12f, 1e-12f);
    u64 ws0 = 0ull, vs0 = 0ull, ws1 = 0ull, vs1 = 0ull;

    const ulonglong2* sh2 = reinterpret_cast<const ulonglong2*>(sh)
                          + (size_t)split * PAIRS_PER_SPLIT * 3;

    #pragma unroll 4
    for (int p = 0; p < PAIRS_PER_SPLIT; p++) {
        ulonglong2 c1 = sh2[p * 3 + 0];  // (nx1, ny1)  LDS.128 broadcast
        ulonglong2 c2 = sh2[p * 3 + 1];  // (nx2, ny2)
        ulonglong2 vv = sh2[p * 3 + 2];  // (vv1, vv2)

        // chain 0 (packs at lane)
        {
            u64 dx1 = f2_add(gx0, c1.x);
            u64 dy1 = f2_add(gy0, c1.y);
            u64 da  = f2_fma(dy1, dy1, eps2);
            da      = f2_fma(dx1, dx1, da);
            u64 dx2 = f2_add(gx0, c2.x);
            u64 dy2 = f2_add(gy0, c2.y);
            u64 db  = f2_fma(dy2, dy2, eps2);
            db      = f2_fma(dx2, dx2, db);
            u64 sum  = f2_add(da, db);
            u64 prod = f2_mul(da, db);
            u64 num  = f2_mul(vv.x, db);
            num      = f2_fma(vv.y, da, num);
            u64 r    = f2_rcp(prod);
            ws0 = f2_fma(sum, r, ws0);
            vs0 = f2_fma(num, r, vs0);
        }
        // chain 1 (packs at lane+32) -- fully independent
        {
            u64 dx1 = f2_add(gx1, c1.x);
            u64 dy1 = f2_add(gy1, c1.y);
            u64 da  = f2_fma(dy1, dy1, eps2);
            da      = f2_fma(dx1, dx1, da);
            u64 dx2 = f2_add(gx1, c2.x);
            u64 dy2 = f2_add(gy1, c2.y);
            u64 db  = f2_fma(dy2, dy2, eps2);
            db      = f2_fma(dx2, dx2, db);
            u64 sum  = f2_add(da, db);
            u64 prod = f2_mul(da, db);
            u64 num  = f2_mul(vv.x, db);
            num      = f2_fma(vv.y, da, num);
            u64 r    = f2_rcp(prod);
            ws1 = f2_fma(sum, r, ws1);
            vs1 = f2_fma(num, r, vs1);
        }
    }

    // Partials -> smem
    {
        float w0, w1, n0, n1;
        f2_unpack(ws0, w0, w1);  f2_unpack(vs0, n0, n1);
        red[split * PACKS_PER_BLOCK + lane] = make_float4(w0, w1, n0, n1);
        f2_unpack(ws1, w0, w1);  f2_unpack(vs1, n0, n1);
        red[split * PACKS_PER_BLOCK + 32 + lane] = make_float4(w0, w1, n0, n1);
    }
    __syncthreads();

    // Threads 0..63 reduce 8 splits for one pack each (fixed order, det.)
    if (tid < PACKS_PER_BLOCK) {
        float4 acc = red[tid];
        #pragma unroll
        for (int k = 1; k < SPLITS; k++) {
            float4 t = red[k * PACKS_PER_BLOCK + tid];  // conflict-free LDS.128
            acc.x += t.x; acc.y += t.y; acc.z += t.z; acc.w += t.w;
        }
        float2 r;
        r.x = acc.z * frcp(acc.x);
        r.y = acc.w * frcp(acc.y);
        reinterpret_cast<float2*>(out)[packbase + tid] = r;
    }
}

extern "C" void kernel_launch(void* const* d_in, const int* in_sizes, int n_in,
                              void* d_out, int out_size) {
    const float* station_coords = (const float*)d_in[0];  // (B,S,2)
    const float* station_values = (const float*)d_in[1];  // (B,S)
    const float* grid_points    = (const float*)d_in[2];  // (B,P,2)
    float* out = (float*)d_out;

    const int S = NSTATIONS;                 // 512 per problem spec
    const int B = in_sizes[1] / S;           // 2
    const int P = in_sizes[2] / (B * 2);     // 131072

    const int blocks = NPACKS / PACKS_PER_BLOCK;  // 2048 blocks, 16384 warps
    idw_fused<<<blocks, TPB>>>(station_coords, station_values, grid_points,
                               out, P);
}